// round 13
// baseline (speedup 1.0000x reference)
#include <cuda_runtime.h>
#include <cuda_fp16.h>
#include <cstdint>

// Problem constants (match reference: N, E, F_IN, H, D)
#define NNODES 50000
#define NEDGES 800000
#define FDIM   128      // F_IN == H*D == 128
#define NHEADS 4
#define HDIM   32
#define SCAN_NB ((NNODES + 1023) / 1024)   // 49

// ---------------- device scratch (no allocations allowed) ----------------
__device__ __align__(16) __half g_hh[NNODES * FDIM];   // x @ W in fp16 (12.8 MB)
__device__ __align__(16) float g_alpha_l[NNODES * NHEADS];
__device__ __align__(16) float g_alpha_r[NNODES * NHEADS];
__device__ __align__(16) float g_w[NEDGES * NHEADS];   // per-edge softmax weights (12.8 MB)
__device__ int   g_cnt[NNODES];                        // histogram, then cursor
__device__ int   g_off[NNODES + 1];                    // CSR offsets by destination
__device__ int   g_src[NEDGES];                        // src per edge, sorted by dst
__device__ int   g_bsum[SCAN_NB];
__device__ int   g_boff[SCAN_NB];
__device__ int   g_is64;                               // edge dtype flag
// W in tf32 mma-fragment layout: [ks(16)][nt(16)][lane(32)] -> (b0,b1)
__device__ __align__(16) uint2 g_wf[16 * 16 * 32];     // 64 KB

__device__ __forceinline__ int clamp_node(int v) {
    v = v < 0 ? 0 : v;
    return v >= NNODES ? NNODES - 1 : v;
}

__device__ __forceinline__ uint32_t f2tf32(float f) {
    uint32_t r;
    asm("cvt.rna.tf32.f32 %0, %1;" : "=r"(r) : "f"(f));
    return r;
}

__device__ __forceinline__ void mma_tf32(float4& d, const uint32_t a0, const uint32_t a1,
                                         const uint32_t a2, const uint32_t a3,
                                         uint32_t b0, uint32_t b1) {
    asm volatile(
        "mma.sync.aligned.m16n8k8.row.col.f32.tf32.tf32.f32 "
        "{%0,%1,%2,%3}, {%4,%5,%6,%7}, {%8,%9}, {%0,%1,%2,%3};"
        : "+f"(d.x), "+f"(d.y), "+f"(d.z), "+f"(d.w)
        : "r"(a0), "r"(a1), "r"(a2), "r"(a3), "r"(b0), "r"(b1));
}

// ---------------- K0 (fused): zero hist + W->tf32 fragments + dtype probe ----
__global__ void k_init(const int* __restrict__ ei32, const float* __restrict__ W) {
    int t = blockIdx.x * blockDim.x + threadIdx.x;
    if (t < NNODES) g_cnt[t] = 0;
    if (t < 16 * 16 * 32) {
        int lane = t & 31;
        int tile = t >> 5;
        int nt = tile & 15;
        int ks = tile >> 4;
        int krow = ks * 8 + (lane & 3);
        int col  = nt * 8 + (lane >> 2);
        uint2 b;
        b.x = f2tf32(W[krow * FDIM + col]);
        b.y = f2tf32(W[(krow + 4) * FDIM + col]);
        g_wf[t] = b;
    }
    if (blockIdx.x == 0 && threadIdx.x < 32) {
        // int64-LE edge data (values < 50000) => all odd int32 words zero
        int v = ei32[2 * threadIdx.x + 1];
        unsigned nz = __ballot_sync(0xffffffffu, v != 0);
        if (threadIdx.x == 0) g_is64 = (nz == 0u) ? 1 : 0;
    }
}

// ---------------- K1: histogram of destinations ----------------
__global__ void k_hist(const int* __restrict__ ei32) {
    int i = blockIdx.x * blockDim.x + threadIdx.x;
    if (i < NEDGES) {
        int idx = NEDGES + i;
        int to = g_is64 ? ei32[2 * idx] : ei32[idx];
        atomicAdd(&g_cnt[clamp_node(to)], 1);
    }
}

// ---------------- K2a: block-local exclusive scan ----------------
__global__ __launch_bounds__(1024) void k_scan1() {
    __shared__ int wsum[32];
    const int tid = threadIdx.x;
    const int lane = tid & 31, wid = tid >> 5;
    const int i = blockIdx.x * 1024 + tid;

    int v = (i < NNODES) ? g_cnt[i] : 0;
    int x = v;
    #pragma unroll
    for (int o = 1; o < 32; o <<= 1) {
        int t = __shfl_up_sync(0xffffffffu, x, o);
        if (lane >= o) x += t;
    }
    if (lane == 31) wsum[wid] = x;
    __syncthreads();
    if (wid == 0) {
        int x2 = wsum[lane];
        #pragma unroll
        for (int o = 1; o < 32; o <<= 1) {
            int t = __shfl_up_sync(0xffffffffu, x2, o);
            if (lane >= o) x2 += t;
        }
        wsum[lane] = x2;
    }
    __syncthreads();
    int add = (wid > 0) ? wsum[wid - 1] : 0;
    int incl = x + add;
    if (i < NNODES) g_off[i] = incl - v;
    if (tid == 1023) g_bsum[blockIdx.x] = incl;
}

// ---------------- K2b: scan the 49 block sums ----------------
__global__ __launch_bounds__(64) void k_scan2() {
    const int tid = threadIdx.x;
    const int lane = tid & 31, wid = tid >> 5;
    __shared__ int w0_total;

    int v = (tid < SCAN_NB) ? g_bsum[tid] : 0;
    int x = v;
    #pragma unroll
    for (int o = 1; o < 32; o <<= 1) {
        int t = __shfl_up_sync(0xffffffffu, x, o);
        if (lane >= o) x += t;
    }
    if (wid == 0 && lane == 31) w0_total = x;
    __syncthreads();
    int base = (wid == 1) ? w0_total : 0;
    if (tid < SCAN_NB) g_boff[tid] = base + x - v;
    if (tid == SCAN_NB - 1) g_off[NNODES] = base + x;
}

// ---------------- K2c: add block offsets; zero cnt ----------------
__global__ __launch_bounds__(1024) void k_scan3() {
    const int i = blockIdx.x * 1024 + threadIdx.x;
    if (i < NNODES) {
        g_off[i] += g_boff[blockIdx.x];
        g_cnt[i] = 0;
    }
}

// ---------------- K4: tensor-core GEMM h = x @ W + fused alpha ----------------
// mma.sync m16n8k8 tf32; x split hi+lo (exact), W pre-rounded to tf32 (g_wf).
// h stored as fp16; alpha from fp32 accs. (Runs BEFORE scatter now.)
__global__ __launch_bounds__(256) void k_gemm(const float* __restrict__ x,
                                              const float* __restrict__ att_l,
                                              const float* __restrict__ att_r) {
    const int wid  = threadIdx.x >> 5;
    const int lane = threadIdx.x & 31;
    const int g = lane >> 2;          // 0..7
    const int c = lane & 3;           // 0..3
    const int row0 = blockIdx.x * 128 + wid * 16;

    const int rA0 = min(row0 + g,     NNODES - 1);
    const int rA1 = min(row0 + g + 8, NNODES - 1);
    const float* xr0 = x + rA0 * FDIM;
    const float* xr1 = x + rA1 * FDIM;

    float4 acc[16];
    #pragma unroll
    for (int nt = 0; nt < 16; nt++) acc[nt] = make_float4(0.f, 0.f, 0.f, 0.f);

    #pragma unroll 4
    for (int ks = 0; ks < 16; ks++) {
        const int k0 = ks * 8;
        float v0 = xr0[k0 + c];
        float v1 = xr1[k0 + c];
        float v2 = xr0[k0 + c + 4];
        float v3 = xr1[k0 + c + 4];
        uint32_t h0 = f2tf32(v0), h1 = f2tf32(v1), h2 = f2tf32(v2), h3 = f2tf32(v3);
        uint32_t l0 = f2tf32(v0 - __uint_as_float(h0));
        uint32_t l1 = f2tf32(v1 - __uint_as_float(h1));
        uint32_t l2 = f2tf32(v2 - __uint_as_float(h2));
        uint32_t l3 = f2tf32(v3 - __uint_as_float(h3));

        const uint2* bf = g_wf + (ks * 16) * 32 + lane;
        #pragma unroll
        for (int nt = 0; nt < 16; nt++) {
            uint2 b = bf[nt * 32];
            mma_tf32(acc[nt], h0, h1, h2, h3, b.x, b.y);
            mma_tf32(acc[nt], l0, l1, l2, l3, b.x, b.y);
        }
    }

    const bool ok0 = (row0 + g)     < NNODES;
    const bool ok1 = (row0 + g + 8) < NNODES;
    __half* hr0 = g_hh + (row0 + g) * FDIM;
    __half* hr1 = g_hh + (row0 + g + 8) * FDIM;
    #pragma unroll
    for (int nt = 0; nt < 16; nt++) {
        int col = nt * 8 + 2 * c;
        if (ok0) *(__half2*)(hr0 + col) = __floats2half2_rn(acc[nt].x, acc[nt].y);
        if (ok1) *(__half2*)(hr1 + col) = __floats2half2_rn(acc[nt].z, acc[nt].w);
    }

    #pragma unroll
    for (int hd = 0; hd < NHEADS; hd++) {
        float plg = 0.f, plg8 = 0.f, prg = 0.f, prg8 = 0.f;
        #pragma unroll
        for (int j = 0; j < 4; j++) {
            int nt = hd * 4 + j;
            int col = nt * 8 + 2 * c;
            float2 al2 = *(const float2*)(att_l + col);
            float2 ar2 = *(const float2*)(att_r + col);
            plg  += acc[nt].x * al2.x + acc[nt].y * al2.y;
            plg8 += acc[nt].z * al2.x + acc[nt].w * al2.y;
            prg  += acc[nt].x * ar2.x + acc[nt].y * ar2.y;
            prg8 += acc[nt].z * ar2.x + acc[nt].w * ar2.y;
        }
        #pragma unroll
        for (int o = 1; o <= 2; o <<= 1) {
            plg  += __shfl_xor_sync(0xffffffffu, plg,  o);
            plg8 += __shfl_xor_sync(0xffffffffu, plg8, o);
            prg  += __shfl_xor_sync(0xffffffffu, prg,  o);
            prg8 += __shfl_xor_sync(0xffffffffu, prg8, o);
        }
        if (c == 0) {
            if (ok0) {
                g_alpha_l[(row0 + g) * NHEADS + hd] = plg;
                g_alpha_r[(row0 + g) * NHEADS + hd] = prg;
            }
            if (ok1) {
                g_alpha_l[(row0 + g + 8) * NHEADS + hd] = plg8;
                g_alpha_r[(row0 + g + 8) * NHEADS + hd] = prg8;
            }
        }
    }
}

// ---------------- K3: scatter edges + precompute per-edge softmax weights ----------
// Runs after GEMM (needs alpha). Edge-parallel: gathers are latency-hidden here.
__global__ void k_scatw(const int* __restrict__ ei32) {
    int i = blockIdx.x * blockDim.x + threadIdx.x;
    if (i < NEDGES) {
        int is64 = g_is64;
        int from = is64 ? ei32[2 * i]            : ei32[i];
        int to   = is64 ? ei32[2 * (NEDGES + i)] : ei32[NEDGES + i];
        from = clamp_node(from);
        to   = clamp_node(to);
        int pos = g_off[to] + atomicAdd(&g_cnt[to], 1);
        pos = pos < 0 ? 0 : (pos >= NEDGES ? NEDGES - 1 : pos);
        g_src[pos] = from;

        float4 al = *(const float4*)&g_alpha_l[from * NHEADS];
        float4 ar = *(const float4*)&g_alpha_r[to * NHEADS];
        float4 w;
        float a;
        a = al.x + ar.x; a = (a > 0.f) ? a : 0.2f * a; w.x = __expf(a);
        a = al.y + ar.y; a = (a > 0.f) ? a : 0.2f * a; w.y = __expf(a);
        a = al.z + ar.z; a = (a > 0.f) ? a : 0.2f * a; w.z = __expf(a);
        a = al.w + ar.w; a = (a > 0.f) ? a : 0.2f * a; w.w = __expf(a);
        *(float4*)&g_w[pos * NHEADS] = w;
    }
}

// ---------------- K5: per-destination weighted aggregation ----------------
// one warp per destination; weights precomputed (sequential loads); the only
// dependent gather per edge is h[s]. Unroll x2 (proven sweet spot).
__global__ __launch_bounds__(256) void k_agg(const float* __restrict__ bias,
                                             float* __restrict__ out) {
    int n = blockIdx.x * 8 + (threadIdx.x >> 5);
    int lane = threadIdx.x & 31;
    if (n >= NNODES) return;

    const int head = lane >> 3;
    const int off0 = g_off[n], off1 = g_off[n + 1];

    float4 acc = make_float4(0.f, 0.f, 0.f, 0.f);
    float den = 0.f;
    const uint2* h2 = (const uint2*)g_hh;   // lane reads 4 halves (8B)

    int e = off0;
    for (; e + 1 < off1; e += 2) {
        int s0 = g_src[e];
        int s1 = g_src[e + 1];
        float w0 = g_w[e * NHEADS + head];
        float w1 = g_w[(e + 1) * NHEADS + head];
        uint2 u0 = h2[s0 * 32 + lane];
        uint2 u1 = h2[s1 * 32 + lane];
        float2 p00 = __half22float2(*(const __half2*)&u0.x);
        float2 p01 = __half22float2(*(const __half2*)&u0.y);
        float2 p10 = __half22float2(*(const __half2*)&u1.x);
        float2 p11 = __half22float2(*(const __half2*)&u1.y);
        acc.x = fmaf(w0, p00.x, fmaf(w1, p10.x, acc.x));
        acc.y = fmaf(w0, p00.y, fmaf(w1, p10.y, acc.y));
        acc.z = fmaf(w0, p01.x, fmaf(w1, p11.x, acc.z));
        acc.w = fmaf(w0, p01.y, fmaf(w1, p11.y, acc.w));
        den += w0 + w1;
    }
    if (e < off1) {
        int s = g_src[e];
        float w = g_w[e * NHEADS + head];
        uint2 u = h2[s * 32 + lane];
        float2 p0 = __half22float2(*(const __half2*)&u.x);
        float2 p1 = __half22float2(*(const __half2*)&u.y);
        acc.x = fmaf(w, p0.x, acc.x);
        acc.y = fmaf(w, p0.y, acc.y);
        acc.z = fmaf(w, p1.x, acc.z);
        acc.w = fmaf(w, p1.y, acc.w);
        den += w;
    }

    float inv = 1.f / (den + 1e-9f);
    float b0 = bias[lane * 4 + 0], b1 = bias[lane * 4 + 1];
    float b2 = bias[lane * 4 + 2], b3 = bias[lane * 4 + 3];
    float4 o;
    o.x = fmaf(acc.x, inv, b0);
    o.y = fmaf(acc.y, inv, b1);
    o.z = fmaf(acc.z, inv, b2);
    o.w = fmaf(acc.w, inv, b3);
    ((float4*)out)[n * 32 + lane] = o;
}

// ---------------- launcher ----------------
extern "C" void kernel_launch(void* const* d_in, const int* in_sizes, int n_in,
                              void* d_out, int out_size) {
    int ix = -1, ie = -1, iw = -1;
    int small_idx[3] = {-1, -1, -1};
    int ns = 0;
    for (int i = 0; i < n_in; i++) {
        int sz = in_sizes[i];
        if      (sz == NNODES * FDIM) ix = i;
        else if (sz == 2 * NEDGES)    ie = i;
        else if (sz == FDIM * FDIM)   iw = i;
        else if (sz == FDIM && ns < 3) small_idx[ns++] = i;
    }
    if (ix < 0 || ie < 0 || iw < 0 || ns < 3) {
        ix = 0; ie = 1; iw = 2;
        small_idx[0] = 3; small_idx[1] = 4; small_idx[2] = 5;
    }

    const float* x     = (const float*)d_in[ix];
    const int*   ei32  = (const int*)d_in[ie];
    const float* W     = (const float*)d_in[iw];
    const float* att_l = (const float*)d_in[small_idx[0]];
    const float* att_r = (const float*)d_in[small_idx[1]];
    const float* bias  = (const float*)d_in[small_idx[2]];
    float*       out   = (float*)d_out;

    k_init<<<(NNODES + 255) / 256, 256>>>(ei32, W);
    k_hist<<<(NEDGES + 255) / 256, 256>>>(ei32);
    k_scan1<<<SCAN_NB, 1024>>>();
    k_scan2<<<1, 64>>>();
    k_scan3<<<SCAN_NB, 1024>>>();
    k_gemm<<<(NNODES + 127) / 128, 256>>>(x, att_l, att_r);
    k_scatw<<<(NEDGES + 255) / 256, 256>>>(ei32);
    k_agg<<<(NNODES + 7) / 8, 256>>>(bias, out);
}

// round 14
// speedup vs baseline: 1.0350x; 1.0350x over previous
#include <cuda_runtime.h>
#include <cuda_fp16.h>
#include <cstdint>

// Problem constants (match reference: N, E, F_IN, H, D)
#define NNODES 50000
#define NEDGES 800000
#define FDIM   128      // F_IN == H*D == 128
#define NHEADS 4
#define HDIM   32
#define SCAN_NB ((NNODES + 1023) / 1024)   // 49

// ---------------- device scratch (no allocations allowed) ----------------
__device__ __align__(16) __half g_hh[NNODES * FDIM];   // x @ W in fp16 (12.8 MB)
__device__ float g_alpha_l[NNODES * NHEADS];
__device__ float g_alpha_r[NNODES * NHEADS];
__device__ int   g_cnt[NNODES];                        // histogram, then cursor
__device__ int   g_off[NNODES + 1];                    // CSR offsets by destination
__device__ int   g_src[NEDGES];                        // src per edge, sorted by dst
__device__ int   g_bsum[SCAN_NB];
__device__ int   g_is64;                               // edge dtype flag
// W in tf32 mma-fragment layout: [ks(16)][nt(16)][lane(32)] -> (b0,b1)
__device__ __align__(16) uint2 g_wf[16 * 16 * 32];     // 64 KB

__device__ __forceinline__ int clamp_node(int v) {
    v = v < 0 ? 0 : v;
    return v >= NNODES ? NNODES - 1 : v;
}

__device__ __forceinline__ uint32_t f2tf32(float f) {
    uint32_t r;
    asm("cvt.rna.tf32.f32 %0, %1;" : "=r"(r) : "f"(f));
    return r;
}

__device__ __forceinline__ void mma_tf32(float4& d, const uint32_t a0, const uint32_t a1,
                                         const uint32_t a2, const uint32_t a3,
                                         uint32_t b0, uint32_t b1) {
    asm volatile(
        "mma.sync.aligned.m16n8k8.row.col.f32.tf32.tf32.f32 "
        "{%0,%1,%2,%3}, {%4,%5,%6,%7}, {%8,%9}, {%0,%1,%2,%3};"
        : "+f"(d.x), "+f"(d.y), "+f"(d.z), "+f"(d.w)
        : "r"(a0), "r"(a1), "r"(a2), "r"(a3), "r"(b0), "r"(b1));
}

// ---------------- K0 (fused): zero hist + W->tf32 fragments + dtype probe ----
__global__ void k_init(const int* __restrict__ ei32, const float* __restrict__ W) {
    int t = blockIdx.x * blockDim.x + threadIdx.x;
    if (t < NNODES) g_cnt[t] = 0;
    if (t == 0) g_off[NNODES] = NEDGES;     // grand total is a constant
    if (t < 16 * 16 * 32) {
        int lane = t & 31;
        int tile = t >> 5;
        int nt = tile & 15;
        int ks = tile >> 4;
        int krow = ks * 8 + (lane & 3);
        int col  = nt * 8 + (lane >> 2);
        uint2 b;
        b.x = f2tf32(W[krow * FDIM + col]);
        b.y = f2tf32(W[(krow + 4) * FDIM + col]);
        g_wf[t] = b;
    }
    if (blockIdx.x == 0 && threadIdx.x < 32) {
        // int64-LE edge data (values < 50000) => all odd int32 words zero
        int v = ei32[2 * threadIdx.x + 1];
        unsigned nz = __ballot_sync(0xffffffffu, v != 0);
        if (threadIdx.x == 0) g_is64 = (nz == 0u) ? 1 : 0;
    }
}

// ---------------- K1: histogram of destinations (4 edges/thread for MLP) ----------
__global__ void k_hist(const int* __restrict__ ei32) {
    int base = (blockIdx.x * blockDim.x + threadIdx.x) * 4;
    if (base >= NEDGES) return;
    const int is64 = g_is64;
    if (base + 3 < NEDGES) {
        int t0, t1, t2, t3;
        if (is64) {
            t0 = ei32[2 * (NEDGES + base)];
            t1 = ei32[2 * (NEDGES + base + 1)];
            t2 = ei32[2 * (NEDGES + base + 2)];
            t3 = ei32[2 * (NEDGES + base + 3)];
        } else {
            int4 t4 = *(const int4*)&ei32[NEDGES + base];
            t0 = t4.x; t1 = t4.y; t2 = t4.z; t3 = t4.w;
        }
        atomicAdd(&g_cnt[clamp_node(t0)], 1);
        atomicAdd(&g_cnt[clamp_node(t1)], 1);
        atomicAdd(&g_cnt[clamp_node(t2)], 1);
        atomicAdd(&g_cnt[clamp_node(t3)], 1);
    } else {
        for (int i = base; i < NEDGES; i++) {
            int to = is64 ? ei32[2 * (NEDGES + i)] : ei32[NEDGES + i];
            atomicAdd(&g_cnt[clamp_node(to)], 1);
        }
    }
}

// ---------------- K2a: block-local exclusive scan ----------------
__global__ __launch_bounds__(1024) void k_scan1() {
    __shared__ int wsum[32];
    const int tid = threadIdx.x;
    const int lane = tid & 31, wid = tid >> 5;
    const int i = blockIdx.x * 1024 + tid;

    int v = (i < NNODES) ? g_cnt[i] : 0;
    int x = v;
    #pragma unroll
    for (int o = 1; o < 32; o <<= 1) {
        int t = __shfl_up_sync(0xffffffffu, x, o);
        if (lane >= o) x += t;
    }
    if (lane == 31) wsum[wid] = x;
    __syncthreads();
    if (wid == 0) {
        int x2 = wsum[lane];
        #pragma unroll
        for (int o = 1; o < 32; o <<= 1) {
            int t = __shfl_up_sync(0xffffffffu, x2, o);
            if (lane >= o) x2 += t;
        }
        wsum[lane] = x2;
    }
    __syncthreads();
    int add = (wid > 0) ? wsum[wid - 1] : 0;
    int incl = x + add;
    if (i < NNODES) g_off[i] = incl - v;    // block-local exclusive
    if (tid == 1023) g_bsum[blockIdx.x] = incl;
}

// ---------------- K2b: add block offsets (computed in-block); zero cnt ----------
// Each block reduces g_bsum[0..bid) itself (<=49 ints, L2-hot) -> no k_scan2.
__global__ __launch_bounds__(1024) void k_scan3() {
    __shared__ int s_w[2];
    const int tid = threadIdx.x;

    if (tid < 64) {
        int v = (tid < (int)blockIdx.x && tid < SCAN_NB) ? g_bsum[tid] : 0;
        #pragma unroll
        for (int o = 16; o >= 1; o >>= 1)
            v += __shfl_xor_sync(0xffffffffu, v, o);
        if ((tid & 31) == 0) s_w[tid >> 5] = v;
    }
    __syncthreads();
    const int boff = s_w[0] + s_w[1];

    const int i = blockIdx.x * 1024 + tid;
    if (i < NNODES) {
        g_off[i] += boff;
        g_cnt[i] = 0;                        // reset for scatter cursor
    }
}

// ---------------- K3: scatter edges into dst-sorted order (4 edges/thread) -------
__global__ void k_scatter(const int* __restrict__ ei32) {
    int base = (blockIdx.x * blockDim.x + threadIdx.x) * 4;
    if (base >= NEDGES) return;
    const int is64 = g_is64;
    if (base + 3 < NEDGES) {
        int f0, f1, f2, f3, t0, t1, t2, t3;
        if (is64) {
            f0 = ei32[2 * base];
            f1 = ei32[2 * (base + 1)];
            f2 = ei32[2 * (base + 2)];
            f3 = ei32[2 * (base + 3)];
            t0 = ei32[2 * (NEDGES + base)];
            t1 = ei32[2 * (NEDGES + base + 1)];
            t2 = ei32[2 * (NEDGES + base + 2)];
            t3 = ei32[2 * (NEDGES + base + 3)];
        } else {
            int4 f4 = *(const int4*)&ei32[base];
            int4 t4 = *(const int4*)&ei32[NEDGES + base];
            f0 = f4.x; f1 = f4.y; f2 = f4.z; f3 = f4.w;
            t0 = t4.x; t1 = t4.y; t2 = t4.z; t3 = t4.w;
        }
        f0 = clamp_node(f0); f1 = clamp_node(f1);
        f2 = clamp_node(f2); f3 = clamp_node(f3);
        t0 = clamp_node(t0); t1 = clamp_node(t1);
        t2 = clamp_node(t2); t3 = clamp_node(t3);
        int p0 = g_off[t0] + atomicAdd(&g_cnt[t0], 1);
        int p1 = g_off[t1] + atomicAdd(&g_cnt[t1], 1);
        int p2 = g_off[t2] + atomicAdd(&g_cnt[t2], 1);
        int p3 = g_off[t3] + atomicAdd(&g_cnt[t3], 1);
        p0 = p0 < 0 ? 0 : (p0 >= NEDGES ? NEDGES - 1 : p0);
        p1 = p1 < 0 ? 0 : (p1 >= NEDGES ? NEDGES - 1 : p1);
        p2 = p2 < 0 ? 0 : (p2 >= NEDGES ? NEDGES - 1 : p2);
        p3 = p3 < 0 ? 0 : (p3 >= NEDGES ? NEDGES - 1 : p3);
        g_src[p0] = f0;
        g_src[p1] = f1;
        g_src[p2] = f2;
        g_src[p3] = f3;
    } else {
        for (int i = base; i < NEDGES; i++) {
            int from = is64 ? ei32[2 * i]            : ei32[i];
            int to   = is64 ? ei32[2 * (NEDGES + i)] : ei32[NEDGES + i];
            from = clamp_node(from);
            to   = clamp_node(to);
            int pos = g_off[to] + atomicAdd(&g_cnt[to], 1);
            pos = pos < 0 ? 0 : (pos >= NEDGES ? NEDGES - 1 : pos);
            g_src[pos] = from;
        }
    }
}

// ---------------- K4: tensor-core GEMM h = x @ W + fused alpha ----------------
// mma.sync m16n8k8 tf32; x split hi+lo (exact), W pre-rounded to tf32 (g_wf).
// h stored as fp16; alpha from fp32 accs. (Exact R9 body.)
__global__ __launch_bounds__(256) void k_gemm(const float* __restrict__ x,
                                              const float* __restrict__ att_l,
                                              const float* __restrict__ att_r) {
    const int wid  = threadIdx.x >> 5;
    const int lane = threadIdx.x & 31;
    const int g = lane >> 2;          // 0..7
    const int c = lane & 3;           // 0..3
    const int row0 = blockIdx.x * 128 + wid * 16;

    const int rA0 = min(row0 + g,     NNODES - 1);
    const int rA1 = min(row0 + g + 8, NNODES - 1);
    const float* xr0 = x + rA0 * FDIM;
    const float* xr1 = x + rA1 * FDIM;

    float4 acc[16];
    #pragma unroll
    for (int nt = 0; nt < 16; nt++) acc[nt] = make_float4(0.f, 0.f, 0.f, 0.f);

    #pragma unroll 4
    for (int ks = 0; ks < 16; ks++) {
        const int k0 = ks * 8;
        float v0 = xr0[k0 + c];
        float v1 = xr1[k0 + c];
        float v2 = xr0[k0 + c + 4];
        float v3 = xr1[k0 + c + 4];
        uint32_t h0 = f2tf32(v0), h1 = f2tf32(v1), h2 = f2tf32(v2), h3 = f2tf32(v3);
        uint32_t l0 = f2tf32(v0 - __uint_as_float(h0));
        uint32_t l1 = f2tf32(v1 - __uint_as_float(h1));
        uint32_t l2 = f2tf32(v2 - __uint_as_float(h2));
        uint32_t l3 = f2tf32(v3 - __uint_as_float(h3));

        const uint2* bf = g_wf + (ks * 16) * 32 + lane;
        #pragma unroll
        for (int nt = 0; nt < 16; nt++) {
            uint2 b = bf[nt * 32];
            mma_tf32(acc[nt], h0, h1, h2, h3, b.x, b.y);
            mma_tf32(acc[nt], l0, l1, l2, l3, b.x, b.y);
        }
    }

    const bool ok0 = (row0 + g)     < NNODES;
    const bool ok1 = (row0 + g + 8) < NNODES;
    __half* hr0 = g_hh + (row0 + g) * FDIM;
    __half* hr1 = g_hh + (row0 + g + 8) * FDIM;
    #pragma unroll
    for (int nt = 0; nt < 16; nt++) {
        int col = nt * 8 + 2 * c;
        if (ok0) *(__half2*)(hr0 + col) = __floats2half2_rn(acc[nt].x, acc[nt].y);
        if (ok1) *(__half2*)(hr1 + col) = __floats2half2_rn(acc[nt].z, acc[nt].w);
    }

    #pragma unroll
    for (int hd = 0; hd < NHEADS; hd++) {
        float plg = 0.f, plg8 = 0.f, prg = 0.f, prg8 = 0.f;
        #pragma unroll
        for (int j = 0; j < 4; j++) {
            int nt = hd * 4 + j;
            int col = nt * 8 + 2 * c;
            float2 al2 = *(const float2*)(att_l + col);
            float2 ar2 = *(const float2*)(att_r + col);
            plg  += acc[nt].x * al2.x + acc[nt].y * al2.y;
            plg8 += acc[nt].z * al2.x + acc[nt].w * al2.y;
            prg  += acc[nt].x * ar2.x + acc[nt].y * ar2.y;
            prg8 += acc[nt].z * ar2.x + acc[nt].w * ar2.y;
        }
        #pragma unroll
        for (int o = 1; o <= 2; o <<= 1) {
            plg  += __shfl_xor_sync(0xffffffffu, plg,  o);
            plg8 += __shfl_xor_sync(0xffffffffu, plg8, o);
            prg  += __shfl_xor_sync(0xffffffffu, prg,  o);
            prg8 += __shfl_xor_sync(0xffffffffu, prg8, o);
        }
        if (c == 0) {
            if (ok0) {
                g_alpha_l[(row0 + g) * NHEADS + hd] = plg;
                g_alpha_r[(row0 + g) * NHEADS + hd] = prg;
            }
            if (ok1) {
                g_alpha_l[(row0 + g + 8) * NHEADS + hd] = plg8;
                g_alpha_r[(row0 + g + 8) * NHEADS + hd] = prg8;
            }
        }
    }
}

// ---------------- K5: per-destination softmax-weighted aggregation ----------------
// one warp per destination; unroll x2 (exact R9 body — proven best).
__global__ __launch_bounds__(256) void k_agg(const float* __restrict__ bias,
                                             float* __restrict__ out) {
    int n = blockIdx.x * 8 + (threadIdx.x >> 5);
    int lane = threadIdx.x & 31;
    if (n >= NNODES) return;

    const int head = lane >> 3;
    const float ar = g_alpha_r[n * NHEADS + head];
    const int off0 = g_off[n], off1 = g_off[n + 1];

    float4 acc = make_float4(0.f, 0.f, 0.f, 0.f);
    float den = 0.f;
    const uint2* h2 = (const uint2*)g_hh;   // lane reads 4 halves (8B)

    int e = off0;
    for (; e + 1 < off1; e += 2) {
        int s0 = g_src[e];
        int s1 = g_src[e + 1];
        float a0 = g_alpha_l[s0 * NHEADS + head] + ar;
        float a1 = g_alpha_l[s1 * NHEADS + head] + ar;
        uint2 u0 = h2[s0 * 32 + lane];
        uint2 u1 = h2[s1 * 32 + lane];
        a0 = (a0 > 0.f) ? a0 : 0.2f * a0;
        a1 = (a1 > 0.f) ? a1 : 0.2f * a1;
        float w0 = __expf(a0);
        float w1 = __expf(a1);
        float2 p00 = __half22float2(*(const __half2*)&u0.x);
        float2 p01 = __half22float2(*(const __half2*)&u0.y);
        float2 p10 = __half22float2(*(const __half2*)&u1.x);
        float2 p11 = __half22float2(*(const __half2*)&u1.y);
        acc.x = fmaf(w0, p00.x, fmaf(w1, p10.x, acc.x));
        acc.y = fmaf(w0, p00.y, fmaf(w1, p10.y, acc.y));
        acc.z = fmaf(w0, p01.x, fmaf(w1, p11.x, acc.z));
        acc.w = fmaf(w0, p01.y, fmaf(w1, p11.y, acc.w));
        den += w0 + w1;
    }
    if (e < off1) {
        int s = g_src[e];
        float a = g_alpha_l[s * NHEADS + head] + ar;
        a = (a > 0.f) ? a : 0.2f * a;
        float w = __expf(a);
        uint2 u = h2[s * 32 + lane];
        float2 p0 = __half22float2(*(const __half2*)&u.x);
        float2 p1 = __half22float2(*(const __half2*)&u.y);
        acc.x = fmaf(w, p0.x, acc.x);
        acc.y = fmaf(w, p0.y, acc.y);
        acc.z = fmaf(w, p1.x, acc.z);
        acc.w = fmaf(w, p1.y, acc.w);
        den += w;
    }

    float inv = 1.f / (den + 1e-9f);
    float b0 = bias[lane * 4 + 0], b1 = bias[lane * 4 + 1];
    float b2 = bias[lane * 4 + 2], b3 = bias[lane * 4 + 3];
    float4 o;
    o.x = fmaf(acc.x, inv, b0);
    o.y = fmaf(acc.y, inv, b1);
    o.z = fmaf(acc.z, inv, b2);
    o.w = fmaf(acc.w, inv, b3);
    ((float4*)out)[n * 32 + lane] = o;
}

// ---------------- launcher ----------------
extern "C" void kernel_launch(void* const* d_in, const int* in_sizes, int n_in,
                              void* d_out, int out_size) {
    int ix = -1, ie = -1, iw = -1;
    int small_idx[3] = {-1, -1, -1};
    int ns = 0;
    for (int i = 0; i < n_in; i++) {
        int sz = in_sizes[i];
        if      (sz == NNODES * FDIM) ix = i;
        else if (sz == 2 * NEDGES)    ie = i;
        else if (sz == FDIM * FDIM)   iw = i;
        else if (sz == FDIM && ns < 3) small_idx[ns++] = i;
    }
    if (ix < 0 || ie < 0 || iw < 0 || ns < 3) {
        ix = 0; ie = 1; iw = 2;
        small_idx[0] = 3; small_idx[1] = 4; small_idx[2] = 5;
    }

    const float* x     = (const float*)d_in[ix];
    const int*   ei32  = (const int*)d_in[ie];
    const float* W     = (const float*)d_in[iw];
    const float* att_l = (const float*)d_in[small_idx[0]];
    const float* att_r = (const float*)d_in[small_idx[1]];
    const float* bias  = (const float*)d_in[small_idx[2]];
    float*       out   = (float*)d_out;

    const int EB = (NEDGES / 4 + 255) / 256;   // 4 edges per thread
    k_init<<<(NNODES + 255) / 256, 256>>>(ei32, W);
    k_hist<<<EB, 256>>>(ei32);
    k_scan1<<<SCAN_NB, 1024>>>();
    k_scan3<<<SCAN_NB, 1024>>>();
    k_scatter<<<EB, 256>>>(ei32);
    k_gemm<<<(NNODES + 127) / 128, 256>>>(x, att_l, att_r);
    k_agg<<<(NNODES + 7) / 8, 256>>>(bias, out);
}

// round 15
// speedup vs baseline: 1.2650x; 1.2221x over previous
#include <cuda_runtime.h>
#include <cuda_fp16.h>
#include <cstdint>

// Problem constants (match reference: N, E, F_IN, H, D)
#define NNODES 50000
#define NEDGES 800000
#define FDIM   128      // F_IN == H*D == 128
#define NHEADS 4
#define HDIM   32
#define SCAN_NB ((NNODES + 1023) / 1024)   // 49

// ---------------- device scratch (no allocations allowed) ----------------
__device__ __align__(16) __half g_hh[NNODES * FDIM];   // x @ W in fp16 (12.8 MB)
__device__ float g_alpha_l[NNODES * NHEADS];
__device__ float g_alpha_r[NNODES * NHEADS];
__device__ int   g_cnt[NNODES];                        // histogram, then cursor
__device__ int   g_off[NNODES + 1];                    // CSR offsets by destination
__device__ int   g_src[NEDGES];                        // src per edge, sorted by dst
__device__ int   g_bsum[SCAN_NB];
__device__ int   g_boff[SCAN_NB];
__device__ int   g_is64;                               // edge dtype flag
// W in tf32 mma-fragment layout: [ks(16)][nt(16)][lane(32)] -> (b0,b1)
__device__ __align__(16) uint2 g_wf[16 * 16 * 32];     // 64 KB

__device__ __forceinline__ int clamp_node(int v) {
    v = v < 0 ? 0 : v;
    return v >= NNODES ? NNODES - 1 : v;
}

__device__ __forceinline__ uint32_t f2tf32(float f) {
    uint32_t r;
    asm("cvt.rna.tf32.f32 %0, %1;" : "=r"(r) : "f"(f));
    return r;
}

__device__ __forceinline__ void mma_tf32(float4& d, const uint32_t a0, const uint32_t a1,
                                         const uint32_t a2, const uint32_t a3,
                                         uint32_t b0, uint32_t b1) {
    asm volatile(
        "mma.sync.aligned.m16n8k8.row.col.f32.tf32.tf32.f32 "
        "{%0,%1,%2,%3}, {%4,%5,%6,%7}, {%8,%9}, {%0,%1,%2,%3};"
        : "+f"(d.x), "+f"(d.y), "+f"(d.z), "+f"(d.w)
        : "r"(a0), "r"(a1), "r"(a2), "r"(a3), "r"(b0), "r"(b1));
}

// ---------------- K0 (fused): zero hist + W->tf32 fragments + dtype probe ----
__global__ void k_init(const int* __restrict__ ei32, const float* __restrict__ W) {
    int t = blockIdx.x * blockDim.x + threadIdx.x;
    if (t < NNODES) g_cnt[t] = 0;
    if (t < 16 * 16 * 32) {
        int lane = t & 31;
        int tile = t >> 5;
        int nt = tile & 15;
        int ks = tile >> 4;
        int krow = ks * 8 + (lane & 3);
        int col  = nt * 8 + (lane >> 2);
        uint2 b;
        b.x = f2tf32(W[krow * FDIM + col]);
        b.y = f2tf32(W[(krow + 4) * FDIM + col]);
        g_wf[t] = b;
    }
    if (blockIdx.x == 0 && threadIdx.x < 32) {
        // int64-LE edge data (values < 50000) => all odd int32 words zero
        int v = ei32[2 * threadIdx.x + 1];
        unsigned nz = __ballot_sync(0xffffffffu, v != 0);
        if (threadIdx.x == 0) g_is64 = (nz == 0u) ? 1 : 0;
    }
}

// ---------------- K1: histogram of destinations ----------------
__global__ void k_hist(const int* __restrict__ ei32) {
    int i = blockIdx.x * blockDim.x + threadIdx.x;
    if (i < NEDGES) {
        int idx = NEDGES + i;
        int to = g_is64 ? ei32[2 * idx] : ei32[idx];
        atomicAdd(&g_cnt[clamp_node(to)], 1);
    }
}

// ---------------- K2a: block-local exclusive scan ----------------
__global__ __launch_bounds__(1024) void k_scan1() {
    __shared__ int wsum[32];
    const int tid = threadIdx.x;
    const int lane = tid & 31, wid = tid >> 5;
    const int i = blockIdx.x * 1024 + tid;

    int v = (i < NNODES) ? g_cnt[i] : 0;
    int x = v;
    #pragma unroll
    for (int o = 1; o < 32; o <<= 1) {
        int t = __shfl_up_sync(0xffffffffu, x, o);
        if (lane >= o) x += t;
    }
    if (lane == 31) wsum[wid] = x;
    __syncthreads();
    if (wid == 0) {
        int x2 = wsum[lane];
        #pragma unroll
        for (int o = 1; o < 32; o <<= 1) {
            int t = __shfl_up_sync(0xffffffffu, x2, o);
            if (lane >= o) x2 += t;
        }
        wsum[lane] = x2;
    }
    __syncthreads();
    int add = (wid > 0) ? wsum[wid - 1] : 0;
    int incl = x + add;
    if (i < NNODES) g_off[i] = incl - v;
    if (tid == 1023) g_bsum[blockIdx.x] = incl;
}

// ---------------- K2b: scan the 49 block sums ----------------
__global__ __launch_bounds__(64) void k_scan2() {
    const int tid = threadIdx.x;
    const int lane = tid & 31, wid = tid >> 5;
    __shared__ int w0_total;

    int v = (tid < SCAN_NB) ? g_bsum[tid] : 0;
    int x = v;
    #pragma unroll
    for (int o = 1; o < 32; o <<= 1) {
        int t = __shfl_up_sync(0xffffffffu, x, o);
        if (lane >= o) x += t;
    }
    if (wid == 0 && lane == 31) w0_total = x;
    __syncthreads();
    int base = (wid == 1) ? w0_total : 0;
    if (tid < SCAN_NB) g_boff[tid] = base + x - v;
    if (tid == SCAN_NB - 1) g_off[NNODES] = base + x;
}

// ---------------- K2c: add block offsets; zero cnt ----------------
__global__ __launch_bounds__(1024) void k_scan3() {
    const int i = blockIdx.x * 1024 + threadIdx.x;
    if (i < NNODES) {
        g_off[i] += g_boff[blockIdx.x];
        g_cnt[i] = 0;
    }
}

// ---------------- K3: scatter edges into dst-sorted order ----------------
__global__ void k_scatter(const int* __restrict__ ei32) {
    int i = blockIdx.x * blockDim.x + threadIdx.x;
    if (i < NEDGES) {
        int is64 = g_is64;
        int from = is64 ? ei32[2 * i]            : ei32[i];
        int to   = is64 ? ei32[2 * (NEDGES + i)] : ei32[NEDGES + i];
        from = clamp_node(from);
        to   = clamp_node(to);
        int pos = g_off[to] + atomicAdd(&g_cnt[to], 1);
        pos = pos < 0 ? 0 : (pos >= NEDGES ? NEDGES - 1 : pos);
        g_src[pos] = from;
    }
}

// ---------------- K4: tensor-core GEMM h = x @ W + fused alpha ----------------
// mma.sync m16n8k8 tf32; x split hi+lo (exact), W pre-rounded to tf32 (g_wf).
// h stored as fp16; alpha from fp32 accs. (Exact R9 body; runs on side stream.)
__global__ __launch_bounds__(256) void k_gemm(const float* __restrict__ x,
                                              const float* __restrict__ att_l,
                                              const float* __restrict__ att_r) {
    const int wid  = threadIdx.x >> 5;
    const int lane = threadIdx.x & 31;
    const int g = lane >> 2;          // 0..7
    const int c = lane & 3;           // 0..3
    const int row0 = blockIdx.x * 128 + wid * 16;

    const int rA0 = min(row0 + g,     NNODES - 1);
    const int rA1 = min(row0 + g + 8, NNODES - 1);
    const float* xr0 = x + rA0 * FDIM;
    const float* xr1 = x + rA1 * FDIM;

    float4 acc[16];
    #pragma unroll
    for (int nt = 0; nt < 16; nt++) acc[nt] = make_float4(0.f, 0.f, 0.f, 0.f);

    #pragma unroll 4
    for (int ks = 0; ks < 16; ks++) {
        const int k0 = ks * 8;
        float v0 = xr0[k0 + c];
        float v1 = xr1[k0 + c];
        float v2 = xr0[k0 + c + 4];
        float v3 = xr1[k0 + c + 4];
        uint32_t h0 = f2tf32(v0), h1 = f2tf32(v1), h2 = f2tf32(v2), h3 = f2tf32(v3);
        uint32_t l0 = f2tf32(v0 - __uint_as_float(h0));
        uint32_t l1 = f2tf32(v1 - __uint_as_float(h1));
        uint32_t l2 = f2tf32(v2 - __uint_as_float(h2));
        uint32_t l3 = f2tf32(v3 - __uint_as_float(h3));

        const uint2* bf = g_wf + (ks * 16) * 32 + lane;
        #pragma unroll
        for (int nt = 0; nt < 16; nt++) {
            uint2 b = bf[nt * 32];
            mma_tf32(acc[nt], h0, h1, h2, h3, b.x, b.y);
            mma_tf32(acc[nt], l0, l1, l2, l3, b.x, b.y);
        }
    }

    const bool ok0 = (row0 + g)     < NNODES;
    const bool ok1 = (row0 + g + 8) < NNODES;
    __half* hr0 = g_hh + (row0 + g) * FDIM;
    __half* hr1 = g_hh + (row0 + g + 8) * FDIM;
    #pragma unroll
    for (int nt = 0; nt < 16; nt++) {
        int col = nt * 8 + 2 * c;
        if (ok0) *(__half2*)(hr0 + col) = __floats2half2_rn(acc[nt].x, acc[nt].y);
        if (ok1) *(__half2*)(hr1 + col) = __floats2half2_rn(acc[nt].z, acc[nt].w);
    }

    #pragma unroll
    for (int hd = 0; hd < NHEADS; hd++) {
        float plg = 0.f, plg8 = 0.f, prg = 0.f, prg8 = 0.f;
        #pragma unroll
        for (int j = 0; j < 4; j++) {
            int nt = hd * 4 + j;
            int col = nt * 8 + 2 * c;
            float2 al2 = *(const float2*)(att_l + col);
            float2 ar2 = *(const float2*)(att_r + col);
            plg  += acc[nt].x * al2.x + acc[nt].y * al2.y;
            plg8 += acc[nt].z * al2.x + acc[nt].w * al2.y;
            prg  += acc[nt].x * ar2.x + acc[nt].y * ar2.y;
            prg8 += acc[nt].z * ar2.x + acc[nt].w * ar2.y;
        }
        #pragma unroll
        for (int o = 1; o <= 2; o <<= 1) {
            plg  += __shfl_xor_sync(0xffffffffu, plg,  o);
            plg8 += __shfl_xor_sync(0xffffffffu, plg8, o);
            prg  += __shfl_xor_sync(0xffffffffu, prg,  o);
            prg8 += __shfl_xor_sync(0xffffffffu, prg8, o);
        }
        if (c == 0) {
            if (ok0) {
                g_alpha_l[(row0 + g) * NHEADS + hd] = plg;
                g_alpha_r[(row0 + g) * NHEADS + hd] = prg;
            }
            if (ok1) {
                g_alpha_l[(row0 + g + 8) * NHEADS + hd] = plg8;
                g_alpha_r[(row0 + g + 8) * NHEADS + hd] = prg8;
            }
        }
    }
}

// ---------------- K5: per-destination softmax-weighted aggregation ----------------
// one warp per destination; unroll x2 (exact R9 body — proven best).
__global__ __launch_bounds__(256) void k_agg(const float* __restrict__ bias,
                                             float* __restrict__ out) {
    int n = blockIdx.x * 8 + (threadIdx.x >> 5);
    int lane = threadIdx.x & 31;
    if (n >= NNODES) return;

    const int head = lane >> 3;
    const float ar = g_alpha_r[n * NHEADS + head];
    const int off0 = g_off[n], off1 = g_off[n + 1];

    float4 acc = make_float4(0.f, 0.f, 0.f, 0.f);
    float den = 0.f;
    const uint2* h2 = (const uint2*)g_hh;   // lane reads 4 halves (8B)

    int e = off0;
    for (; e + 1 < off1; e += 2) {
        int s0 = g_src[e];
        int s1 = g_src[e + 1];
        float a0 = g_alpha_l[s0 * NHEADS + head] + ar;
        float a1 = g_alpha_l[s1 * NHEADS + head] + ar;
        uint2 u0 = h2[s0 * 32 + lane];
        uint2 u1 = h2[s1 * 32 + lane];
        a0 = (a0 > 0.f) ? a0 : 0.2f * a0;
        a1 = (a1 > 0.f) ? a1 : 0.2f * a1;
        float w0 = __expf(a0);
        float w1 = __expf(a1);
        float2 p00 = __half22float2(*(const __half2*)&u0.x);
        float2 p01 = __half22float2(*(const __half2*)&u0.y);
        float2 p10 = __half22float2(*(const __half2*)&u1.x);
        float2 p11 = __half22float2(*(const __half2*)&u1.y);
        acc.x = fmaf(w0, p00.x, fmaf(w1, p10.x, acc.x));
        acc.y = fmaf(w0, p00.y, fmaf(w1, p10.y, acc.y));
        acc.z = fmaf(w0, p01.x, fmaf(w1, p11.x, acc.z));
        acc.w = fmaf(w0, p01.y, fmaf(w1, p11.y, acc.w));
        den += w0 + w1;
    }
    if (e < off1) {
        int s = g_src[e];
        float a = g_alpha_l[s * NHEADS + head] + ar;
        a = (a > 0.f) ? a : 0.2f * a;
        float w = __expf(a);
        uint2 u = h2[s * 32 + lane];
        float2 p0 = __half22float2(*(const __half2*)&u.x);
        float2 p1 = __half22float2(*(const __half2*)&u.y);
        acc.x = fmaf(w, p0.x, acc.x);
        acc.y = fmaf(w, p0.y, acc.y);
        acc.z = fmaf(w, p1.x, acc.z);
        acc.w = fmaf(w, p1.y, acc.w);
        den += w;
    }

    float inv = 1.f / (den + 1e-9f);
    float b0 = bias[lane * 4 + 0], b1 = bias[lane * 4 + 1];
    float b2 = bias[lane * 4 + 2], b3 = bias[lane * 4 + 3];
    float4 o;
    o.x = fmaf(acc.x, inv, b0);
    o.y = fmaf(acc.y, inv, b1);
    o.z = fmaf(acc.z, inv, b2);
    o.w = fmaf(acc.w, inv, b3);
    ((float4*)out)[n * 32 + lane] = o;
}

// ---------------- launcher: fork GEMM onto a side stream (capture-legal) ----------
extern "C" void kernel_launch(void* const* d_in, const int* in_sizes, int n_in,
                              void* d_out, int out_size) {
    int ix = -1, ie = -1, iw = -1;
    int small_idx[3] = {-1, -1, -1};
    int ns = 0;
    for (int i = 0; i < n_in; i++) {
        int sz = in_sizes[i];
        if      (sz == NNODES * FDIM) ix = i;
        else if (sz == 2 * NEDGES)    ie = i;
        else if (sz == FDIM * FDIM)   iw = i;
        else if (sz == FDIM && ns < 3) small_idx[ns++] = i;
    }
    if (ix < 0 || ie < 0 || iw < 0 || ns < 3) {
        ix = 0; ie = 1; iw = 2;
        small_idx[0] = 3; small_idx[1] = 4; small_idx[2] = 5;
    }

    const float* x     = (const float*)d_in[ix];
    const int*   ei32  = (const int*)d_in[ie];
    const float* W     = (const float*)d_in[iw];
    const float* att_l = (const float*)d_in[small_idx[0]];
    const float* att_r = (const float*)d_in[small_idx[1]];
    const float* bias  = (const float*)d_in[small_idx[2]];
    float*       out   = (float*)d_out;

    // Side stream + fork/join events. Created fresh each call (deterministic,
    // host-side only — no device allocations). Not destroyed: a stream/event
    // participating in an ongoing capture must stay alive until EndCapture;
    // kernel_launch is invoked only a handful of times, so the leak is bounded.
    cudaStream_t sB;
    cudaStreamCreateWithFlags(&sB, cudaStreamNonBlocking);
    cudaEvent_t evFork, evJoin;
    cudaEventCreateWithFlags(&evFork, cudaEventDisableTiming);
    cudaEventCreateWithFlags(&evJoin, cudaEventDisableTiming);

    k_init<<<(NNODES + 255) / 256, 256>>>(ei32, W);            // main stream

    cudaEventRecord(evFork, 0);
    cudaStreamWaitEvent(sB, evFork, 0);
    k_gemm<<<(NNODES + 127) / 128, 256, 0, sB>>>(x, att_l, att_r);  // side stream
    cudaEventRecord(evJoin, sB);

    // Edge-sort chain on main stream, concurrent with GEMM:
    k_hist<<<(NEDGES + 255) / 256, 256>>>(ei32);
    k_scan1<<<SCAN_NB, 1024>>>();
    k_scan2<<<1, 64>>>();
    k_scan3<<<SCAN_NB, 1024>>>();
    k_scatter<<<(NEDGES + 255) / 256, 256>>>(ei32);

    cudaStreamWaitEvent(0, evJoin, 0);                          // join
    k_agg<<<(NNODES + 7) / 8, 256>>>(bias, out);
}